// round 3
// baseline (speedup 1.0000x reference)
#include <cuda_runtime.h>

#define NN 50000
#define EE 800000
#define NEG_BIG (-3.402823e38f)

// ---------------- scratch (static __device__, no allocation) ----------------
__device__ float4 g_xh1[NN * 64];    // [N,256] as float4, layer1 linear out
__device__ float4 g_out1[NN * 64];   // [N,256] ELU(agg1 + b1)
__device__ float4 g_a1s[NN];         // a_src per head (4)
__device__ float4 g_a1d[NN];         // a_dst per head (4)
__device__ float  g_xh2[NN * 16];
__device__ float  g_a2s[NN];
__device__ float  g_a2d[NN];
__device__ int    g_cnt[NN];
__device__ int    g_rowptr[NN + 1];
__device__ int    g_cursor[NN];
__device__ int    g_esrc[EE];

// ---------------- CSR build ----------------
__global__ void k_zero() {
    int i = blockIdx.x * blockDim.x + threadIdx.x;
    if (i < NN) g_cnt[i] = 0;
}

__global__ void k_count(const int* __restrict__ ei) {
    int e = blockIdx.x * blockDim.x + threadIdx.x;
    if (e < EE) {
        int t = ei[EE + e];
        atomicAdd(&g_cnt[t], 1);
    }
}

__global__ void k_scan() {
    __shared__ int sums[1024];
    const int C = 49;  // 1024*49 = 50176 >= NN
    int tid = threadIdx.x;
    int start = tid * C;
    int end = start + C; if (end > NN) end = NN;
    int s = 0;
    for (int i = start; i < end; i++) s += g_cnt[i];
    sums[tid] = s;
    __syncthreads();
    for (int off = 1; off < 1024; off <<= 1) {
        int v = (tid >= off) ? sums[tid - off] : 0;
        __syncthreads();
        sums[tid] += v;
        __syncthreads();
    }
    int run = (tid == 0) ? 0 : sums[tid - 1];
    for (int i = start; i < end; i++) {
        g_rowptr[i] = run;
        g_cursor[i] = run;
        run += g_cnt[i];
    }
    if (tid == 1023) g_rowptr[NN] = sums[1023];
}

__global__ void k_scatter(const int* __restrict__ ei) {
    int e = blockIdx.x * blockDim.x + threadIdx.x;
    if (e < EE) {
        int s = ei[e];
        int t = ei[EE + e];
        int p = atomicAdd(&g_cursor[t], 1);
        g_esrc[p] = s;
    }
}

// ---------------- GEMM1: xh1 = x[N,64] @ W1[64,256] ----------------
// grid (ceil(N/32), 2), block 128. Each block: 32 rows x 128 cols.
__global__ __launch_bounds__(128) void k_gemm1(const float* __restrict__ x,
                                               const float* __restrict__ W1) {
    __shared__ float Ws[64 * 128];   // 32 KB
    __shared__ float Xs[32][64];     // 8 KB
    int cOff = blockIdx.y * 128;
    int rowOff = blockIdx.x * 32;
    int tid = threadIdx.x;

    // load W half-tile (2048 float4)
    for (int i = tid; i < 2048; i += 128) {
        int k = i >> 5;           // 4i/128
        int c = (i & 31) << 2;    // 4i%128
        *(float4*)&Ws[k * 128 + c] = *(const float4*)&W1[k * 256 + cOff + c];
    }
    // load x tile (512 float4)
    for (int i = tid; i < 512; i += 128) {
        int r = i >> 4;
        int k = (i & 15) << 2;
        float4 v = make_float4(0.f, 0.f, 0.f, 0.f);
        if (rowOff + r < NN) v = *(const float4*)&x[(rowOff + r) * 64 + k];
        *(float4*)&Xs[r][k] = v;
    }
    __syncthreads();

    int warp = tid >> 5, lane = tid & 31;
    float4 acc[8];
#pragma unroll
    for (int r = 0; r < 8; r++) acc[r] = make_float4(0.f, 0.f, 0.f, 0.f);
    const float4* WsV = (const float4*)Ws;
    for (int k = 0; k < 64; k++) {
        float4 w = WsV[k * 32 + lane];
#pragma unroll
        for (int r = 0; r < 8; r++) {
            float xv = Xs[warp * 8 + r][k];
            acc[r].x += xv * w.x;
            acc[r].y += xv * w.y;
            acc[r].z += xv * w.z;
            acc[r].w += xv * w.w;
        }
    }
#pragma unroll
    for (int r = 0; r < 8; r++) {
        int row = rowOff + warp * 8 + r;
        if (row < NN) g_xh1[row * 64 + (cOff >> 2) + lane] = acc[r];
    }
}

// ---------------- attention dots layer 1 ----------------
// warp per node: a_src1[n][h] = sum_d xh1[n,h,d]*att_s[h,d]
__global__ void k_att1(const float* __restrict__ att_s,
                       const float* __restrict__ att_d) {
    int warp = threadIdx.x >> 5, lane = threadIdx.x & 31;
    int n = blockIdx.x * 8 + warp;
    if (n >= NN) return;
    const float* xh = (const float*)&g_xh1[n * 64];
    float sv[4], dv[4];
#pragma unroll
    for (int h = 0; h < 4; h++) {
        int b = h * 64;
        float x0 = xh[b + lane], x1 = xh[b + lane + 32];
        sv[h] = x0 * att_s[b + lane] + x1 * att_s[b + lane + 32];
        dv[h] = x0 * att_d[b + lane] + x1 * att_d[b + lane + 32];
    }
#pragma unroll
    for (int off = 16; off > 0; off >>= 1) {
#pragma unroll
        for (int h = 0; h < 4; h++) {
            sv[h] += __shfl_xor_sync(0xffffffffu, sv[h], off);
            dv[h] += __shfl_xor_sync(0xffffffffu, dv[h], off);
        }
    }
    if (lane == 0) {
        g_a1s[n] = make_float4(sv[0], sv[1], sv[2], sv[3]);
        g_a1d[n] = make_float4(dv[0], dv[1], dv[2], dv[3]);
    }
}

__device__ __forceinline__ float lrelu(float e) { return e > 0.f ? e : 0.2f * e; }

// ---------------- layer1 aggregate: warp per dst node ----------------
__global__ __launch_bounds__(128) void k_agg1(const float* __restrict__ b1) {
    int warp = threadIdx.x >> 5, lane = threadIdx.x & 31;
    int t = blockIdx.x * 4 + warp;
    if (t >= NN) return;
    int base = g_rowptr[t];
    int deg = g_rowptr[t + 1] - base;
    int total = deg + 1;  // + self loop
    float4 ad = g_a1d[t];

    // pass A: per-head online softmax stats over this lane's edge subset
    float m0 = NEG_BIG, m1 = NEG_BIG, m2 = NEG_BIG, m3 = NEG_BIG;
    float s0 = 0.f, s1 = 0.f, s2 = 0.f, s3 = 0.f;
    for (int j = lane; j < total; j += 32) {
        int s = (j < deg) ? g_esrc[base + j] : t;
        float4 a = g_a1s[s];
        float e;
        e = lrelu(a.x + ad.x);
        if (e > m0) { s0 = s0 * __expf(m0 - e) + 1.f; m0 = e; } else s0 += __expf(e - m0);
        e = lrelu(a.y + ad.y);
        if (e > m1) { s1 = s1 * __expf(m1 - e) + 1.f; m1 = e; } else s1 += __expf(e - m1);
        e = lrelu(a.z + ad.z);
        if (e > m2) { s2 = s2 * __expf(m2 - e) + 1.f; m2 = e; } else s2 += __expf(e - m2);
        e = lrelu(a.w + ad.w);
        if (e > m3) { s3 = s3 * __expf(m3 - e) + 1.f; m3 = e; } else s3 += __expf(e - m3);
    }
    // warp combine (butterfly -> all lanes hold final (m,s))
#pragma unroll
    for (int off = 16; off > 0; off >>= 1) {
        float mo, so, mn;
        mo = __shfl_xor_sync(0xffffffffu, m0, off); so = __shfl_xor_sync(0xffffffffu, s0, off);
        mn = fmaxf(m0, mo); s0 = s0 * __expf(m0 - mn) + so * __expf(mo - mn); m0 = mn;
        mo = __shfl_xor_sync(0xffffffffu, m1, off); so = __shfl_xor_sync(0xffffffffu, s1, off);
        mn = fmaxf(m1, mo); s1 = s1 * __expf(m1 - mn) + so * __expf(mo - mn); m1 = mn;
        mo = __shfl_xor_sync(0xffffffffu, m2, off); so = __shfl_xor_sync(0xffffffffu, s2, off);
        mn = fmaxf(m2, mo); s2 = s2 * __expf(m2 - mn) + so * __expf(mo - mn); m2 = mn;
        mo = __shfl_xor_sync(0xffffffffu, m3, off); so = __shfl_xor_sync(0xffffffffu, s3, off);
        mn = fmaxf(m3, mo); s3 = s3 * __expf(m3 - mn) + so * __expf(mo - mn); m3 = mn;
    }
    float r0 = 1.f / (s0 + 1e-16f), r1 = 1.f / (s1 + 1e-16f);
    float r2 = 1.f / (s2 + 1e-16f), r3 = 1.f / (s3 + 1e-16f);

    // pass B: lane computes alpha for head (lane&3), shfl to feature owners
    int myh = lane & 3;
    float mh = myh == 0 ? m0 : (myh == 1 ? m1 : (myh == 2 ? m2 : m3));
    float rh = myh == 0 ? r0 : (myh == 1 ? r1 : (myh == 2 ? r2 : r3));
    float adh = myh == 0 ? ad.x : (myh == 1 ? ad.y : (myh == 2 ? ad.z : ad.w));
    int h1 = lane >> 4;  // head of float4 #1 (0/1); head of #2 = h1+2

    float4 acc0 = make_float4(0.f, 0.f, 0.f, 0.f);
    float4 acc1 = make_float4(0.f, 0.f, 0.f, 0.f);
    for (int j = 0; j < total; j++) {
        int s = (j < deg) ? g_esrc[base + j] : t;
        float4 a = g_a1s[s];
        float ash = myh == 0 ? a.x : (myh == 1 ? a.y : (myh == 2 ? a.z : a.w));
        float e = lrelu(ash + adh);
        float al = __expf(e - mh) * rh;
        float aH1 = __shfl_sync(0xffffffffu, al, h1);
        float aH2 = __shfl_sync(0xffffffffu, al, h1 + 2);
        const float4* row = &g_xh1[s * 64];
        float4 v1 = row[lane];
        float4 v2 = row[32 + lane];
        acc0.x += aH1 * v1.x; acc0.y += aH1 * v1.y; acc0.z += aH1 * v1.z; acc0.w += aH1 * v1.w;
        acc1.x += aH2 * v2.x; acc1.y += aH2 * v2.y; acc1.z += aH2 * v2.z; acc1.w += aH2 * v2.w;
    }
    // + bias, ELU, store
    float4 bb0 = *(const float4*)&b1[4 * lane];
    float4 bb1 = *(const float4*)&b1[128 + 4 * lane];
    float4 o0, o1;
    float v;
    v = acc0.x + bb0.x; o0.x = v > 0.f ? v : __expf(v) - 1.f;
    v = acc0.y + bb0.y; o0.y = v > 0.f ? v : __expf(v) - 1.f;
    v = acc0.z + bb0.z; o0.z = v > 0.f ? v : __expf(v) - 1.f;
    v = acc0.w + bb0.w; o0.w = v > 0.f ? v : __expf(v) - 1.f;
    v = acc1.x + bb1.x; o1.x = v > 0.f ? v : __expf(v) - 1.f;
    v = acc1.y + bb1.y; o1.y = v > 0.f ? v : __expf(v) - 1.f;
    v = acc1.z + bb1.z; o1.z = v > 0.f ? v : __expf(v) - 1.f;
    v = acc1.w + bb1.w; o1.w = v > 0.f ? v : __expf(v) - 1.f;
    g_out1[t * 64 + lane] = o0;
    g_out1[t * 64 + 32 + lane] = o1;
}

// ---------------- GEMM2 + att2: xh2 = out1[N,256] @ W2[256,16] ----------------
// thread per node, acc[16] in regs, W2 broadcast from shared.
__global__ __launch_bounds__(256) void k_gemm2(const float* __restrict__ W2,
                                               const float* __restrict__ as2,
                                               const float* __restrict__ ad2) {
    __shared__ float Ws[256 * 16];   // 16 KB, [k][c]
    __shared__ float atts[16], attd[16];
    int tid = threadIdx.x;
    for (int i = tid; i < 1024; i += 256)
        ((float4*)Ws)[i] = ((const float4*)W2)[i];
    if (tid < 16) { atts[tid] = as2[tid]; attd[tid] = ad2[tid]; }
    __syncthreads();

    int n = blockIdx.x * 256 + tid;
    if (n >= NN) return;
    float4 acc[4];
#pragma unroll
    for (int i = 0; i < 4; i++) acc[i] = make_float4(0.f, 0.f, 0.f, 0.f);
    const float4* hrow = (const float4*)&g_out1[n * 64];
    const float4* WsV = (const float4*)Ws;
    for (int k4 = 0; k4 < 64; k4++) {
        float4 h4 = hrow[k4];
#pragma unroll
        for (int kk = 0; kk < 4; kk++) {
            float hv = kk == 0 ? h4.x : (kk == 1 ? h4.y : (kk == 2 ? h4.z : h4.w));
            const float4* wr = &WsV[(k4 * 4 + kk) * 4];
#pragma unroll
            for (int q = 0; q < 4; q++) {
                float4 w = wr[q];
                acc[q].x += hv * w.x; acc[q].y += hv * w.y;
                acc[q].z += hv * w.z; acc[q].w += hv * w.w;
            }
        }
    }
    float as = 0.f, ad = 0.f;
#pragma unroll
    for (int q = 0; q < 4; q++) {
        as += acc[q].x * atts[4 * q + 0] + acc[q].y * atts[4 * q + 1] +
              acc[q].z * atts[4 * q + 2] + acc[q].w * atts[4 * q + 3];
        ad += acc[q].x * attd[4 * q + 0] + acc[q].y * attd[4 * q + 1] +
              acc[q].z * attd[4 * q + 2] + acc[q].w * attd[4 * q + 3];
    }
    g_a2s[n] = as;
    g_a2d[n] = ad;
    float4* o = (float4*)&g_xh2[n * 16];
#pragma unroll
    for (int q = 0; q < 4; q++) o[q] = acc[q];
}

// ---------------- layer2 aggregate + bias + log_softmax ----------------
__global__ void k_agg2(const float* __restrict__ b2, float* __restrict__ out) {
    int warp = threadIdx.x >> 5, lane = threadIdx.x & 31;
    int t = blockIdx.x * 8 + warp;
    if (t >= NN) return;
    int base = g_rowptr[t];
    int deg = g_rowptr[t + 1] - base;
    int total = deg + 1;
    float adt = g_a2d[t];

    float m = NEG_BIG, ss = 0.f;
    for (int j = lane; j < total; j += 32) {
        int s = (j < deg) ? g_esrc[base + j] : t;
        float e = lrelu(g_a2s[s] + adt);
        if (e > m) { ss = ss * __expf(m - e) + 1.f; m = e; } else ss += __expf(e - m);
    }
#pragma unroll
    for (int off = 16; off > 0; off >>= 1) {
        float mo = __shfl_xor_sync(0xffffffffu, m, off);
        float so = __shfl_xor_sync(0xffffffffu, ss, off);
        float mn = fmaxf(m, mo);
        ss = ss * __expf(m - mn) + so * __expf(mo - mn);
        m = mn;
    }
    float rcp = 1.f / (ss + 1e-16f);

    float acc = 0.f;
    for (int j = 0; j < total; j++) {
        int s = (j < deg) ? g_esrc[base + j] : t;
        float e = lrelu(g_a2s[s] + adt);
        float al = __expf(e - m) * rcp;
        if (lane < 16) acc += al * g_xh2[s * 16 + lane];
    }
    float v = acc + b2[lane & 15];
    // log_softmax over lanes 0..15 (width-16 shuffles)
    float mx = v;
#pragma unroll
    for (int off = 8; off > 0; off >>= 1)
        mx = fmaxf(mx, __shfl_xor_sync(0xffffffffu, mx, off, 16));
    float ex = __expf(v - mx);
#pragma unroll
    for (int off = 8; off > 0; off >>= 1)
        ex += __shfl_xor_sync(0xffffffffu, ex, off, 16);
    if (lane < 16) out[t * 16 + lane] = v - mx - __logf(ex);
}

// ---------------- launch ----------------
extern "C" void kernel_launch(void* const* d_in, const int* in_sizes, int n_in,
                              void* d_out, int out_size) {
    const float* x    = (const float*)d_in[0];
    const int*   ei   = (const int*)d_in[1];    // JAX default: int64 request -> int32 arrays
    const float* W1   = (const float*)d_in[2];
    const float* as1  = (const float*)d_in[3];
    const float* ad1  = (const float*)d_in[4];
    const float* b1   = (const float*)d_in[5];
    const float* W2   = (const float*)d_in[6];
    const float* as2  = (const float*)d_in[7];
    const float* ad2  = (const float*)d_in[8];
    const float* b2   = (const float*)d_in[9];
    float* out = (float*)d_out;

    (void)in_sizes; (void)n_in; (void)out_size;

    // CSR build (per-launch, deterministic counts; intra-bucket order only
    // permutes fp32 summation order, well within 1e-3 tolerance)
    k_zero<<<(NN + 255) / 256, 256>>>();
    k_count<<<(EE + 255) / 256, 256>>>(ei);
    k_scan<<<1, 1024>>>();
    k_scatter<<<(EE + 255) / 256, 256>>>(ei);

    // layer 1
    dim3 g1((NN + 31) / 32, 2);
    k_gemm1<<<g1, 128>>>(x, W1);
    k_att1<<<(NN + 7) / 8, 256>>>(as1, ad1);
    k_agg1<<<(NN + 3) / 4, 128>>>(b1);

    // layer 2
    k_gemm2<<<(NN + 255) / 256, 256>>>(W2, as2, ad2);
    k_agg2<<<(NN + 7) / 8, 256>>>(b2, out);
}

// round 11
// speedup vs baseline: 1.0407x; 1.0407x over previous
#include <cuda_runtime.h>
#include <cuda_fp16.h>

#define NN 50000
#define EE 800000
#define NEG_BIG (-3.402823e38f)

// ---------------- scratch (static __device__, no allocation) ----------------
__device__ unsigned int g_xh1h[NN * 128]; // [N,256] fp16 (half2-packed), layer1 linear out
__device__ float4 g_out1[NN * 64];        // [N,256] ELU(agg1 + b1), fp32
__device__ float4 g_a1s[NN];              // a_src per head (4)
__device__ float4 g_a1d[NN];              // a_dst per head (4)
__device__ float  g_xh2[NN * 16];
__device__ float  g_a2s[NN];
__device__ float  g_a2d[NN];
__device__ int    g_cnt[NN];
__device__ int    g_rowptr[NN + 1];
__device__ int    g_cursor[NN];
__device__ int    g_esrc[EE];

// ---------------- CSR build ----------------
__global__ void k_zero() {
    int i = blockIdx.x * blockDim.x + threadIdx.x;
    if (i < NN) g_cnt[i] = 0;
}

__global__ void k_count(const int* __restrict__ ei) {
    int e = blockIdx.x * blockDim.x + threadIdx.x;
    if (e < EE) {
        int t = ei[EE + e];
        atomicAdd(&g_cnt[t], 1);
    }
}

__global__ void k_scan() {
    __shared__ int sums[1024];
    const int C = 49;  // 1024*49 = 50176 >= NN
    int tid = threadIdx.x;
    int start = tid * C;
    int end = start + C; if (end > NN) end = NN;
    int s = 0;
    for (int i = start; i < end; i++) s += g_cnt[i];
    sums[tid] = s;
    __syncthreads();
    for (int off = 1; off < 1024; off <<= 1) {
        int v = (tid >= off) ? sums[tid - off] : 0;
        __syncthreads();
        sums[tid] += v;
        __syncthreads();
    }
    int run = (tid == 0) ? 0 : sums[tid - 1];
    for (int i = start; i < end; i++) {
        g_rowptr[i] = run;
        g_cursor[i] = run;
        run += g_cnt[i];
    }
    if (tid == 1023) g_rowptr[NN] = sums[1023];
}

__global__ void k_scatter(const int* __restrict__ ei) {
    int e = blockIdx.x * blockDim.x + threadIdx.x;
    if (e < EE) {
        int s = ei[e];
        int t = ei[EE + e];
        int p = atomicAdd(&g_cursor[t], 1);
        g_esrc[p] = s;
    }
}

// ---------------- GEMM1 + att1 fused: xh1 = x[N,64] @ W1[64,256] ----------------
// grid (ceil(N/32), 2), block 128. Each block: 32 rows x 128 cols (= 2 heads).
// Epilogue: store fp16 xh1, compute per-head attention dots (no atomics —
// blockIdx.y=0 owns heads 0,1; y=1 owns heads 2,3; disjoint float components).
__global__ __launch_bounds__(128) void k_gemm1(const float* __restrict__ x,
                                               const float* __restrict__ W1,
                                               const float* __restrict__ att_s,
                                               const float* __restrict__ att_d) {
    __shared__ float Ws[64 * 128];   // 32 KB
    __shared__ float Xs[32][64];     // 8 KB
    int cOff = blockIdx.y * 128;
    int rowOff = blockIdx.x * 32;
    int tid = threadIdx.x;

    for (int i = tid; i < 2048; i += 128) {
        int k = i >> 5;
        int c = (i & 31) << 2;
        *(float4*)&Ws[k * 128 + c] = *(const float4*)&W1[k * 256 + cOff + c];
    }
    for (int i = tid; i < 512; i += 128) {
        int r = i >> 4;
        int k = (i & 15) << 2;
        float4 v = make_float4(0.f, 0.f, 0.f, 0.f);
        if (rowOff + r < NN) v = *(const float4*)&x[(rowOff + r) * 64 + k];
        *(float4*)&Xs[r][k] = v;
    }
    __syncthreads();

    int warp = tid >> 5, lane = tid & 31;
    float4 acc[8];
#pragma unroll
    for (int r = 0; r < 8; r++) acc[r] = make_float4(0.f, 0.f, 0.f, 0.f);
    const float4* WsV = (const float4*)Ws;
    for (int k = 0; k < 64; k++) {
        float4 w = WsV[k * 32 + lane];
#pragma unroll
        for (int r = 0; r < 8; r++) {
            float xv = Xs[warp * 8 + r][k];
            acc[r].x += xv * w.x;
            acc[r].y += xv * w.y;
            acc[r].z += xv * w.z;
            acc[r].w += xv * w.w;
        }
    }

    // epilogue: fp16 store + attention partial dots
    float4 as4 = *(const float4*)&att_s[cOff + 4 * lane];
    float4 ad4 = *(const float4*)&att_d[cOff + 4 * lane];
#pragma unroll
    for (int r = 0; r < 8; r++) {
        int row = rowOff + warp * 8 + r;
        if (row < NN) {   // uniform across warp
            __half2 ha = __floats2half2_rn(acc[r].x, acc[r].y);
            __half2 hb = __floats2half2_rn(acc[r].z, acc[r].w);
            uint2 p = make_uint2(*(unsigned*)&ha, *(unsigned*)&hb);
            *(uint2*)&g_xh1h[row * 128 + (cOff >> 1) + lane * 2] = p;

            float sv = acc[r].x * as4.x + acc[r].y * as4.y +
                       acc[r].z * as4.z + acc[r].w * as4.w;
            float dv = acc[r].x * ad4.x + acc[r].y * ad4.y +
                       acc[r].z * ad4.z + acc[r].w * ad4.w;
#pragma unroll
            for (int off = 8; off > 0; off >>= 1) {
                sv += __shfl_xor_sync(0xffffffffu, sv, off);
                dv += __shfl_xor_sync(0xffffffffu, dv, off);
            }
            if ((lane & 15) == 0) {
                int h = (cOff >> 6) + (lane >> 4);   // 0..3, disjoint per block/half-warp
                ((float*)&g_a1s[row])[h] = sv;
                ((float*)&g_a1d[row])[h] = dv;
            }
        }
    }
}

__device__ __forceinline__ float lrelu(float e) { return e > 0.f ? e : 0.2f * e; }

// ---------------- layer1 aggregate: warp per dst node ----------------
// Gather fp16 rows (512B/edge). Each lane owns feats 8*lane..8*lane+7,
// all in head lane>>3, so every lane computes its own alpha (no shfl in loop).
__global__ __launch_bounds__(256) void k_agg1(const float* __restrict__ b1) {
    int warp = threadIdx.x >> 5, lane = threadIdx.x & 31;
    int t = blockIdx.x * 8 + warp;
    if (t >= NN) return;
    int base = g_rowptr[t];
    int deg = g_rowptr[t + 1] - base;
    int total = deg + 1;  // + self loop
    float4 ad = g_a1d[t];

    // pass A: per-head online softmax stats over this lane's edge subset
    float m0 = NEG_BIG, m1 = NEG_BIG, m2 = NEG_BIG, m3 = NEG_BIG;
    float s0 = 0.f, s1 = 0.f, s2 = 0.f, s3 = 0.f;
    for (int j = lane; j < total; j += 32) {
        int s = (j < deg) ? g_esrc[base + j] : t;
        float4 a = g_a1s[s];
        float e;
        e = lrelu(a.x + ad.x);
        if (e > m0) { s0 = s0 * __expf(m0 - e) + 1.f; m0 = e; } else s0 += __expf(e - m0);
        e = lrelu(a.y + ad.y);
        if (e > m1) { s1 = s1 * __expf(m1 - e) + 1.f; m1 = e; } else s1 += __expf(e - m1);
        e = lrelu(a.z + ad.z);
        if (e > m2) { s2 = s2 * __expf(m2 - e) + 1.f; m2 = e; } else s2 += __expf(e - m2);
        e = lrelu(a.w + ad.w);
        if (e > m3) { s3 = s3 * __expf(m3 - e) + 1.f; m3 = e; } else s3 += __expf(e - m3);
    }
#pragma unroll
    for (int off = 16; off > 0; off >>= 1) {
        float mo, so, mn;
        mo = __shfl_xor_sync(0xffffffffu, m0, off); so = __shfl_xor_sync(0xffffffffu, s0, off);
        mn = fmaxf(m0, mo); s0 = s0 * __expf(m0 - mn) + so * __expf(mo - mn); m0 = mn;
        mo = __shfl_xor_sync(0xffffffffu, m1, off); so = __shfl_xor_sync(0xffffffffu, s1, off);
        mn = fmaxf(m1, mo); s1 = s1 * __expf(m1 - mn) + so * __expf(mo - mn); m1 = mn;
        mo = __shfl_xor_sync(0xffffffffu, m2, off); so = __shfl_xor_sync(0xffffffffu, s2, off);
        mn = fmaxf(m2, mo); s2 = s2 * __expf(m2 - mn) + so * __expf(mo - mn); m2 = mn;
        mo = __shfl_xor_sync(0xffffffffu, m3, off); so = __shfl_xor_sync(0xffffffffu, s3, off);
        mn = fmaxf(m3, mo); s3 = s3 * __expf(m3 - mn) + so * __expf(mo - mn); m3 = mn;
    }

    // per-lane head selection (lane>>3)
    int myh = lane >> 3;
    float mh  = myh == 0 ? m0 : (myh == 1 ? m1 : (myh == 2 ? m2 : m3));
    float ssh = myh == 0 ? s0 : (myh == 1 ? s1 : (myh == 2 ? s2 : s3));
    float adh = myh == 0 ? ad.x : (myh == 1 ? ad.y : (myh == 2 ? ad.z : ad.w));
    float rh = 1.f / (ssh + 1e-16f);

    // pass B: gather fp16 rows, each lane weights its 8 feats by its head's alpha
    float2 a0 = make_float2(0.f, 0.f), a1 = make_float2(0.f, 0.f);
    float2 a2 = make_float2(0.f, 0.f), a3 = make_float2(0.f, 0.f);
    const uint4* xh = (const uint4*)g_xh1h;
#pragma unroll 4
    for (int j = 0; j < total; j++) {
        int s = (j < deg) ? g_esrc[base + j] : t;
        float4 a = g_a1s[s];
        float ash = myh == 0 ? a.x : (myh == 1 ? a.y : (myh == 2 ? a.z : a.w));
        float e = lrelu(ash + adh);
        float al = __expf(e - mh) * rh;
        uint4 v = xh[s * 32 + lane];
        float2 f;
        f = __half22float2(*(__half2*)&v.x); a0.x += al * f.x; a0.y += al * f.y;
        f = __half22float2(*(__half2*)&v.y); a1.x += al * f.x; a1.y += al * f.y;
        f = __half22float2(*(__half2*)&v.z); a2.x += al * f.x; a2.y += al * f.y;
        f = __half22float2(*(__half2*)&v.w); a3.x += al * f.x; a3.y += al * f.y;
    }

    // + bias, ELU, store (feats 8*lane..8*lane+7 -> float4s 2*lane, 2*lane+1)
    float4 bb0 = *(const float4*)&b1[8 * lane];
    float4 bb1 = *(const float4*)&b1[8 * lane + 4];
    float4 o0, o1;
    float v;
    v = a0.x + bb0.x; o0.x = v > 0.f ? v : __expf(v) - 1.f;
    v = a0.y + bb0.y; o0.y = v > 0.f ? v : __expf(v) - 1.f;
    v = a1.x + bb0.z; o0.z = v > 0.f ? v : __expf(v) - 1.f;
    v = a1.y + bb0.w; o0.w = v > 0.f ? v : __expf(v) - 1.f;
    v = a2.x + bb1.x; o1.x = v > 0.f ? v : __expf(v) - 1.f;
    v = a2.y + bb1.y; o1.y = v > 0.f ? v : __expf(v) - 1.f;
    v = a3.x + bb1.z; o1.z = v > 0.f ? v : __expf(v) - 1.f;
    v = a3.y + bb1.w; o1.w = v > 0.f ? v : __expf(v) - 1.f;
    g_out1[t * 64 + 2 * lane] = o0;
    g_out1[t * 64 + 2 * lane + 1] = o1;
}

// ---------------- GEMM2 + att2: xh2 = out1[N,256] @ W2[256,16] ----------------
__global__ __launch_bounds__(256) void k_gemm2(const float* __restrict__ W2,
                                               const float* __restrict__ as2,
                                               const float* __restrict__ ad2) {
    __shared__ float Ws[256 * 16];
    __shared__ float atts[16], attd[16];
    int tid = threadIdx.x;
    for (int i = tid; i < 1024; i += 256)
        ((float4*)Ws)[i] = ((const float4*)W2)[i];
    if (tid < 16) { atts[tid] = as2[tid]; attd[tid] = ad2[tid]; }
    __syncthreads();

    int n = blockIdx.x * 256 + tid;
    if (n >= NN) return;
    float4 acc[4];
#pragma unroll
    for (int i = 0; i < 4; i++) acc[i] = make_float4(0.f, 0.f, 0.f, 0.f);
    const float4* hrow = (const float4*)&g_out1[n * 64];
    const float4* WsV = (const float4*)Ws;
    for (int k4 = 0; k4 < 64; k4++) {
        float4 h4 = hrow[k4];
#pragma unroll
        for (int kk = 0; kk < 4; kk++) {
            float hv = kk == 0 ? h4.x : (kk == 1 ? h4.y : (kk == 2 ? h4.z : h4.w));
            const float4* wr = &WsV[(k4 * 4 + kk) * 4];
#pragma unroll
            for (int q = 0; q < 4; q++) {
                float4 w = wr[q];
                acc[q].x += hv * w.x; acc[q].y += hv * w.y;
                acc[q].z += hv * w.z; acc[q].w += hv * w.w;
            }
        }
    }
    float as = 0.f, ad = 0.f;
#pragma unroll
    for (int q = 0; q < 4; q++) {
        as += acc[q].x * atts[4 * q + 0] + acc[q].y * atts[4 * q + 1] +
              acc[q].z * atts[4 * q + 2] + acc[q].w * atts[4 * q + 3];
        ad += acc[q].x * attd[4 * q + 0] + acc[q].y * attd[4 * q + 1] +
              acc[q].z * attd[4 * q + 2] + acc[q].w * attd[4 * q + 3];
    }
    g_a2s[n] = as;
    g_a2d[n] = ad;
    float4* o = (float4*)&g_xh2[n * 16];
#pragma unroll
    for (int q = 0; q < 4; q++) o[q] = acc[q];
}

// ---------------- layer2 aggregate + bias + log_softmax ----------------
__global__ void k_agg2(const float* __restrict__ b2, float* __restrict__ out) {
    int warp = threadIdx.x >> 5, lane = threadIdx.x & 31;
    int t = blockIdx.x * 8 + warp;
    if (t >= NN) return;
    int base = g_rowptr[t];
    int deg = g_rowptr[t + 1] - base;
    int total = deg + 1;
    float adt = g_a2d[t];

    float m = NEG_BIG, ss = 0.f;
    for (int j = lane; j < total; j += 32) {
        int s = (j < deg) ? g_esrc[base + j] : t;
        float e = lrelu(g_a2s[s] + adt);
        if (e > m) { ss = ss * __expf(m - e) + 1.f; m = e; } else ss += __expf(e - m);
    }
#pragma unroll
    for (int off = 16; off > 0; off >>= 1) {
        float mo = __shfl_xor_sync(0xffffffffu, m, off);
        float so = __shfl_xor_sync(0xffffffffu, ss, off);
        float mn = fmaxf(m, mo);
        ss = ss * __expf(m - mn) + so * __expf(mo - mn);
        m = mn;
    }
    float rcp = 1.f / (ss + 1e-16f);

    float acc = 0.f;
    for (int j = 0; j < total; j++) {
        int s = (j < deg) ? g_esrc[base + j] : t;
        float e = lrelu(g_a2s[s] + adt);
        float al = __expf(e - m) * rcp;
        if (lane < 16) acc += al * g_xh2[s * 16 + lane];
    }
    float v = acc + b2[lane & 15];
    float mx = v;
#pragma unroll
    for (int off = 8; off > 0; off >>= 1)
        mx = fmaxf(mx, __shfl_xor_sync(0xffffffffu, mx, off, 16));
    float ex = __expf(v - mx);
#pragma unroll
    for (int off = 8; off > 0; off >>= 1)
        ex += __shfl_xor_sync(0xffffffffu, ex, off, 16);
    if (lane < 16) out[t * 16 + lane] = v - mx - __logf(ex);
}

// ---------------- launch ----------------
extern "C" void kernel_launch(void* const* d_in, const int* in_sizes, int n_in,
                              void* d_out, int out_size) {
    const float* x    = (const float*)d_in[0];
    const int*   ei   = (const int*)d_in[1];    // int32 (JAX x64 disabled)
    const float* W1   = (const float*)d_in[2];
    const float* as1  = (const float*)d_in[3];
    const float* ad1  = (const float*)d_in[4];
    const float* b1   = (const float*)d_in[5];
    const float* W2   = (const float*)d_in[6];
    const float* as2  = (const float*)d_in[7];
    const float* ad2  = (const float*)d_in[8];
    const float* b2   = (const float*)d_in[9];
    float* out = (float*)d_out;

    (void)in_sizes; (void)n_in; (void)out_size;

    // CSR build
    k_zero<<<(NN + 255) / 256, 256>>>();
    k_count<<<(EE + 255) / 256, 256>>>(ei);
    k_scan<<<1, 1024>>>();
    k_scatter<<<(EE + 255) / 256, 256>>>(ei);

    // layer 1 (att1 fused into gemm1 epilogue)
    dim3 g1((NN + 31) / 32, 2);
    k_gemm1<<<g1, 128>>>(x, W1, as1, ad1);
    k_agg1<<<(NN + 7) / 8, 256>>>(b1);

    // layer 2
    k_gemm2<<<(NN + 255) / 256, 256>>>(W2, as2, ad2);
    k_agg2<<<(NN + 7) / 8, 256>>>(b2, out);
}

// round 13
// speedup vs baseline: 1.3196x; 1.2680x over previous
#include <cuda_runtime.h>
#include <cuda_fp16.h>

#define NN 50000
#define EE 800000
#define NB 196              // ceil(NN/256) scan blocks
#define NEG_BIG (-3.402823e38f)

// ---------------- scratch (static __device__, no allocation) ----------------
__device__ unsigned int g_xh1h[NN * 128]; // [N,256] fp16 (half2-packed), layer1 linear out
__device__ float4 g_out1[NN * 64];        // [N,256] ELU(agg1 + b1), fp32
__device__ float4 g_a1s[NN];              // a_src per head (4)
__device__ float4 g_a1d[NN];              // a_dst per head (4)
__device__ float  g_xh2[NN * 16];
__device__ float  g_a2s[NN];
__device__ float  g_a2d[NN];
__device__ int    g_cnt[NN];
__device__ int    g_rowptr[NN + 1];
__device__ int    g_cursor[NN];
__device__ int    g_esrc[EE];
__device__ int    g_bsum[NB];
__device__ int    g_boff[NB];

// ---------------- CSR build ----------------
__global__ void k_zero() {
    int i = blockIdx.x * blockDim.x + threadIdx.x;
    if (i < NN) g_cnt[i] = 0;
}

__global__ void k_count(const int* __restrict__ ei) {
    int e = blockIdx.x * blockDim.x + threadIdx.x;
    if (e < EE) {
        int t = ei[EE + e];
        atomicAdd(&g_cnt[t], 1);
    }
}

// parallel coalesced scan, 3 kernels
__global__ __launch_bounds__(256) void k_scan1() {
    __shared__ int sm[256];
    int tid = threadIdx.x;
    int i = blockIdx.x * 256 + tid;
    int v = (i < NN) ? g_cnt[i] : 0;
    sm[tid] = v;
    __syncthreads();
#pragma unroll
    for (int off = 1; off < 256; off <<= 1) {
        int u = (tid >= off) ? sm[tid - off] : 0;
        __syncthreads();
        sm[tid] += u;
        __syncthreads();
    }
    if (i < NN) g_rowptr[i] = sm[tid] - v;   // exclusive, block-local
    if (tid == 255) g_bsum[blockIdx.x] = sm[255];
}

__global__ __launch_bounds__(256) void k_scan2() {
    __shared__ int sm[256];
    int tid = threadIdx.x;
    int v = (tid < NB) ? g_bsum[tid] : 0;
    sm[tid] = v;
    __syncthreads();
#pragma unroll
    for (int off = 1; off < 256; off <<= 1) {
        int u = (tid >= off) ? sm[tid - off] : 0;
        __syncthreads();
        sm[tid] += u;
        __syncthreads();
    }
    if (tid < NB) g_boff[tid] = sm[tid] - v;
    if (tid == 255) g_rowptr[NN] = sm[255];   // total edge count
}

__global__ __launch_bounds__(256) void k_scan3() {
    int i = blockIdx.x * 256 + threadIdx.x;
    if (i < NN) {
        int val = g_rowptr[i] + g_boff[blockIdx.x];
        g_rowptr[i] = val;
        g_cursor[i] = val;
    }
}

__global__ void k_scatter(const int* __restrict__ ei) {
    int e = blockIdx.x * blockDim.x + threadIdx.x;
    if (e < EE) {
        int s = ei[e];
        int t = ei[EE + e];
        int p = atomicAdd(&g_cursor[t], 1);
        g_esrc[p] = s;
    }
}

// ---------------- GEMM1 + att1 fused: xh1 = x[N,64] @ W1[64,256] ----------------
// grid (ceil(N/32), 2), block 128. Each block: 32 rows x 128 cols (= 2 heads).
__global__ __launch_bounds__(128) void k_gemm1(const float* __restrict__ x,
                                               const float* __restrict__ W1,
                                               const float* __restrict__ att_s,
                                               const float* __restrict__ att_d) {
    __shared__ float Ws[64 * 128];   // 32 KB
    __shared__ float Xs[32][64];     // 8 KB
    int cOff = blockIdx.y * 128;
    int rowOff = blockIdx.x * 32;
    int tid = threadIdx.x;

    for (int i = tid; i < 2048; i += 128) {
        int k = i >> 5;
        int c = (i & 31) << 2;
        *(float4*)&Ws[k * 128 + c] = *(const float4*)&W1[k * 256 + cOff + c];
    }
    for (int i = tid; i < 512; i += 128) {
        int r = i >> 4;
        int k = (i & 15) << 2;
        float4 v = make_float4(0.f, 0.f, 0.f, 0.f);
        if (rowOff + r < NN) v = *(const float4*)&x[(rowOff + r) * 64 + k];
        *(float4*)&Xs[r][k] = v;
    }
    __syncthreads();

    int warp = tid >> 5, lane = tid & 31;
    float4 acc[8];
#pragma unroll
    for (int r = 0; r < 8; r++) acc[r] = make_float4(0.f, 0.f, 0.f, 0.f);
    const float4* WsV = (const float4*)Ws;
    for (int k = 0; k < 64; k++) {
        float4 w = WsV[k * 32 + lane];
#pragma unroll
        for (int r = 0; r < 8; r++) {
            float xv = Xs[warp * 8 + r][k];
            acc[r].x += xv * w.x;
            acc[r].y += xv * w.y;
            acc[r].z += xv * w.z;
            acc[r].w += xv * w.w;
        }
    }

    // epilogue: fp16 store + attention partial dots
    float4 as4 = *(const float4*)&att_s[cOff + 4 * lane];
    float4 ad4 = *(const float4*)&att_d[cOff + 4 * lane];
#pragma unroll
    for (int r = 0; r < 8; r++) {
        int row = rowOff + warp * 8 + r;
        if (row < NN) {   // uniform across warp
            __half2 ha = __floats2half2_rn(acc[r].x, acc[r].y);
            __half2 hb = __floats2half2_rn(acc[r].z, acc[r].w);
            uint2 p = make_uint2(*(unsigned*)&ha, *(unsigned*)&hb);
            *(uint2*)&g_xh1h[row * 128 + (cOff >> 1) + lane * 2] = p;

            float sv = acc[r].x * as4.x + acc[r].y * as4.y +
                       acc[r].z * as4.z + acc[r].w * as4.w;
            float dv = acc[r].x * ad4.x + acc[r].y * ad4.y +
                       acc[r].z * ad4.z + acc[r].w * ad4.w;
#pragma unroll
            for (int off = 8; off > 0; off >>= 1) {
                sv += __shfl_xor_sync(0xffffffffu, sv, off);
                dv += __shfl_xor_sync(0xffffffffu, dv, off);
            }
            if ((lane & 15) == 0) {
                int h = (cOff >> 6) + (lane >> 4);   // 0..3, disjoint per block/half-warp
                ((float*)&g_a1s[row])[h] = sv;
                ((float*)&g_a1d[row])[h] = dv;
            }
        }
    }
}

__device__ __forceinline__ float lrelu(float e) { return e > 0.f ? e : 0.2f * e; }

// ---------------- layer1 aggregate: warp per dst node ----------------
__global__ __launch_bounds__(256) void k_agg1(const float* __restrict__ b1) {
    int warp = threadIdx.x >> 5, lane = threadIdx.x & 31;
    int t = blockIdx.x * 8 + warp;
    if (t >= NN) return;
    int base = g_rowptr[t];
    int deg = g_rowptr[t + 1] - base;
    int total = deg + 1;  // + self loop
    float4 ad = g_a1d[t];

    // pass A: per-head online softmax stats over this lane's edge subset
    float m0 = NEG_BIG, m1 = NEG_BIG, m2 = NEG_BIG, m3 = NEG_BIG;
    float s0 = 0.f, s1 = 0.f, s2 = 0.f, s3 = 0.f;
    for (int j = lane; j < total; j += 32) {
        int s = (j < deg) ? g_esrc[base + j] : t;
        float4 a = g_a1s[s];
        float e;
        e = lrelu(a.x + ad.x);
        if (e > m0) { s0 = s0 * __expf(m0 - e) + 1.f; m0 = e; } else s0 += __expf(e - m0);
        e = lrelu(a.y + ad.y);
        if (e > m1) { s1 = s1 * __expf(m1 - e) + 1.f; m1 = e; } else s1 += __expf(e - m1);
        e = lrelu(a.z + ad.z);
        if (e > m2) { s2 = s2 * __expf(m2 - e) + 1.f; m2 = e; } else s2 += __expf(e - m2);
        e = lrelu(a.w + ad.w);
        if (e > m3) { s3 = s3 * __expf(m3 - e) + 1.f; m3 = e; } else s3 += __expf(e - m3);
    }
#pragma unroll
    for (int off = 16; off > 0; off >>= 1) {
        float mo, so, mn;
        mo = __shfl_xor_sync(0xffffffffu, m0, off); so = __shfl_xor_sync(0xffffffffu, s0, off);
        mn = fmaxf(m0, mo); s0 = s0 * __expf(m0 - mn) + so * __expf(mo - mn); m0 = mn;
        mo = __shfl_xor_sync(0xffffffffu, m1, off); so = __shfl_xor_sync(0xffffffffu, s1, off);
        mn = fmaxf(m1, mo); s1 = s1 * __expf(m1 - mn) + so * __expf(mo - mn); m1 = mn;
        mo = __shfl_xor_sync(0xffffffffu, m2, off); so = __shfl_xor_sync(0xffffffffu, s2, off);
        mn = fmaxf(m2, mo); s2 = s2 * __expf(m2 - mn) + so * __expf(mo - mn); m2 = mn;
        mo = __shfl_xor_sync(0xffffffffu, m3, off); so = __shfl_xor_sync(0xffffffffu, s3, off);
        mn = fmaxf(m3, mo); s3 = s3 * __expf(m3 - mn) + so * __expf(mo - mn); m3 = mn;
    }

    // per-lane head selection (lane>>3)
    int myh = lane >> 3;
    float mh  = myh == 0 ? m0 : (myh == 1 ? m1 : (myh == 2 ? m2 : m3));
    float ssh = myh == 0 ? s0 : (myh == 1 ? s1 : (myh == 2 ? s2 : s3));
    float adh = myh == 0 ? ad.x : (myh == 1 ? ad.y : (myh == 2 ? ad.z : ad.w));
    float rh = 1.f / (ssh + 1e-16f);

    // pass B: gather fp16 rows, each lane weights its 8 feats by its head's alpha
    float2 a0 = make_float2(0.f, 0.f), a1 = make_float2(0.f, 0.f);
    float2 a2 = make_float2(0.f, 0.f), a3 = make_float2(0.f, 0.f);
    const uint4* xh = (const uint4*)g_xh1h;
#pragma unroll 4
    for (int j = 0; j < total; j++) {
        int s = (j < deg) ? g_esrc[base + j] : t;
        float4 a = g_a1s[s];
        float ash = myh == 0 ? a.x : (myh == 1 ? a.y : (myh == 2 ? a.z : a.w));
        float e = lrelu(ash + adh);
        float al = __expf(e - mh) * rh;
        uint4 v = xh[s * 32 + lane];
        float2 f;
        f = __half22float2(*(__half2*)&v.x); a0.x += al * f.x; a0.y += al * f.y;
        f = __half22float2(*(__half2*)&v.y); a1.x += al * f.x; a1.y += al * f.y;
        f = __half22float2(*(__half2*)&v.z); a2.x += al * f.x; a2.y += al * f.y;
        f = __half22float2(*(__half2*)&v.w); a3.x += al * f.x; a3.y += al * f.y;
    }

    // + bias, ELU, store (feats 8*lane..8*lane+7 -> float4s 2*lane, 2*lane+1)
    float4 bb0 = *(const float4*)&b1[8 * lane];
    float4 bb1 = *(const float4*)&b1[8 * lane + 4];
    float4 o0, o1;
    float v;
    v = a0.x + bb0.x; o0.x = v > 0.f ? v : __expf(v) - 1.f;
    v = a0.y + bb0.y; o0.y = v > 0.f ? v : __expf(v) - 1.f;
    v = a1.x + bb0.z; o0.z = v > 0.f ? v : __expf(v) - 1.f;
    v = a1.y + bb0.w; o0.w = v > 0.f ? v : __expf(v) - 1.f;
    v = a2.x + bb1.x; o1.x = v > 0.f ? v : __expf(v) - 1.f;
    v = a2.y + bb1.y; o1.y = v > 0.f ? v : __expf(v) - 1.f;
    v = a3.x + bb1.z; o1.z = v > 0.f ? v : __expf(v) - 1.f;
    v = a3.y + bb1.w; o1.w = v > 0.f ? v : __expf(v) - 1.f;
    g_out1[t * 64 + 2 * lane] = o0;
    g_out1[t * 64 + 2 * lane + 1] = o1;
}

// ---------------- GEMM2 + att2: xh2 = out1[N,256] @ W2[256,16] ----------------
__global__ __launch_bounds__(256) void k_gemm2(const float* __restrict__ W2,
                                               const float* __restrict__ as2,
                                               const float* __restrict__ ad2) {
    __shared__ float Ws[256 * 16];
    __shared__ float atts[16], attd[16];
    int tid = threadIdx.x;
    for (int i = tid; i < 1024; i += 256)
        ((float4*)Ws)[i] = ((const float4*)W2)[i];
    if (tid < 16) { atts[tid] = as2[tid]; attd[tid] = ad2[tid]; }
    __syncthreads();

    int n = blockIdx.x * 256 + tid;
    if (n >= NN) return;
    float4 acc[4];
#pragma unroll
    for (int i = 0; i < 4; i++) acc[i] = make_float4(0.f, 0.f, 0.f, 0.f);
    const float4* hrow = (const float4*)&g_out1[n * 64];
    const float4* WsV = (const float4*)Ws;
    for (int k4 = 0; k4 < 64; k4++) {
        float4 h4 = hrow[k4];
#pragma unroll
        for (int kk = 0; kk < 4; kk++) {
            float hv = kk == 0 ? h4.x : (kk == 1 ? h4.y : (kk == 2 ? h4.z : h4.w));
            const float4* wr = &WsV[(k4 * 4 + kk) * 4];
#pragma unroll
            for (int q = 0; q < 4; q++) {
                float4 w = wr[q];
                acc[q].x += hv * w.x; acc[q].y += hv * w.y;
                acc[q].z += hv * w.z; acc[q].w += hv * w.w;
            }
        }
    }
    float as = 0.f, ad = 0.f;
#pragma unroll
    for (int q = 0; q < 4; q++) {
        as += acc[q].x * atts[4 * q + 0] + acc[q].y * atts[4 * q + 1] +
              acc[q].z * atts[4 * q + 2] + acc[q].w * atts[4 * q + 3];
        ad += acc[q].x * attd[4 * q + 0] + acc[q].y * attd[4 * q + 1] +
              acc[q].z * attd[4 * q + 2] + acc[q].w * attd[4 * q + 3];
    }
    g_a2s[n] = as;
    g_a2d[n] = ad;
    float4* o = (float4*)&g_xh2[n * 16];
#pragma unroll
    for (int q = 0; q < 4; q++) o[q] = acc[q];
}

// ---------------- layer2 aggregate + bias + log_softmax ----------------
__global__ void k_agg2(const float* __restrict__ b2, float* __restrict__ out) {
    int warp = threadIdx.x >> 5, lane = threadIdx.x & 31;
    int t = blockIdx.x * 8 + warp;
    if (t >= NN) return;
    int base = g_rowptr[t];
    int deg = g_rowptr[t + 1] - base;
    int total = deg + 1;
    float adt = g_a2d[t];

    float m = NEG_BIG, ss = 0.f;
    for (int j = lane; j < total; j += 32) {
        int s = (j < deg) ? g_esrc[base + j] : t;
        float e = lrelu(g_a2s[s] + adt);
        if (e > m) { ss = ss * __expf(m - e) + 1.f; m = e; } else ss += __expf(e - m);
    }
#pragma unroll
    for (int off = 16; off > 0; off >>= 1) {
        float mo = __shfl_xor_sync(0xffffffffu, m, off);
        float so = __shfl_xor_sync(0xffffffffu, ss, off);
        float mn = fmaxf(m, mo);
        ss = ss * __expf(m - mn) + so * __expf(mo - mn);
        m = mn;
    }
    float rcp = 1.f / (ss + 1e-16f);

    float acc = 0.f;
    for (int j = 0; j < total; j++) {
        int s = (j < deg) ? g_esrc[base + j] : t;
        float e = lrelu(g_a2s[s] + adt);
        float al = __expf(e - m) * rcp;
        if (lane < 16) acc += al * g_xh2[s * 16 + lane];
    }
    float v = acc + b2[lane & 15];
    float mx = v;
#pragma unroll
    for (int off = 8; off > 0; off >>= 1)
        mx = fmaxf(mx, __shfl_xor_sync(0xffffffffu, mx, off, 16));
    float ex = __expf(v - mx);
#pragma unroll
    for (int off = 8; off > 0; off >>= 1)
        ex += __shfl_xor_sync(0xffffffffu, ex, off, 16);
    if (lane < 16) out[t * 16 + lane] = v - mx - __logf(ex);
}

// ---------------- launch ----------------
extern "C" void kernel_launch(void* const* d_in, const int* in_sizes, int n_in,
                              void* d_out, int out_size) {
    const float* x    = (const float*)d_in[0];
    const int*   ei   = (const int*)d_in[1];    // int32 (JAX x64 disabled)
    const float* W1   = (const float*)d_in[2];
    const float* as1  = (const float*)d_in[3];
    const float* ad1  = (const float*)d_in[4];
    const float* b1   = (const float*)d_in[5];
    const float* W2   = (const float*)d_in[6];
    const float* as2  = (const float*)d_in[7];
    const float* ad2  = (const float*)d_in[8];
    const float* b2   = (const float*)d_in[9];
    float* out = (float*)d_out;

    (void)in_sizes; (void)n_in; (void)out_size;

    // CSR build (parallel 3-kernel scan); gemm1 interleaved (independent of CSR)
    // so the ncu capture slot lands on k_gemm1.
    k_zero<<<(NN + 255) / 256, 256>>>();
    k_count<<<(EE + 255) / 256, 256>>>(ei);
    k_scan1<<<NB, 256>>>();
    dim3 g1((NN + 31) / 32, 2);
    k_gemm1<<<g1, 128>>>(x, W1, as1, ad1);
    k_scan2<<<1, 256>>>();
    k_scan3<<<NB, 256>>>();
    k_scatter<<<(EE + 255) / 256, 256>>>(ei);

    // layer 1 aggregate
    k_agg1<<<(NN + 7) / 8, 256>>>(b1);

    // layer 2
    k_gemm2<<<(NN + 255) / 256, 256>>>(W2, as2, ad2);
    k_agg2<<<(NN + 7) / 8, 256>>>(b2, out);
}